// round 4
// baseline (speedup 1.0000x reference)
#include <cuda_runtime.h>

#define MAXN 100000
#define MAXE 1600000
#define HID 64
#define SCAN_BLK 1024   // elements per scan block
#define MAX_SCAN_BLOCKS 256

// ---- scratch (device globals; no allocation allowed) ----
__device__ __align__(256) float g_t[MAXN * HID];      // h @ W
__device__ __align__(256) float g_agg[MAXN * HID];    // aggregated messages
__device__ __align__(256) float g_dis[MAXN];          // deg^{-1/2}
__device__ __align__(256) int   g_deg[MAXN];
__device__ __align__(256) int   g_rowptr[MAXN + 1];   // CSR row pointers (by dst)
__device__ __align__(256) int   g_cursor[MAXN];       // binning cursors
__device__ __align__(256) int   g_blocksum[MAX_SCAN_BLOCKS];
__device__ __align__(256) int   g_blockoff[MAX_SCAN_BLOCKS];
__device__ __align__(256) int   g_csrc[MAXE + 4];     // CSR: src per slot (+4 pad, stays 0)
__device__ __align__(256) float g_cnorm[MAXE + 4];    // CSR: edge norm per slot

// ---------------- prep ----------------
__global__ void count_deg_kernel(const int* __restrict__ dst, int E) {
    int e = blockIdx.x * blockDim.x + threadIdx.x;
    if (e < E) atomicAdd(&g_deg[dst[e]], 1);
}

__global__ void compute_dis_kernel(int n) {
    int i = blockIdx.x * blockDim.x + threadIdx.x;
    if (i < n) g_dis[i] = rsqrtf((float)(g_deg[i] + 1));  // +1 self loop
}

// ---- exclusive scan of g_deg -> g_rowptr (3 kernels) ----
__global__ void scan_part_kernel(int n) {
    __shared__ int sm[256];
    int tid = threadIdx.x;
    int base = blockIdx.x * SCAN_BLK + tid * 4;
    int v[4];
#pragma unroll
    for (int j = 0; j < 4; j++) v[j] = (base + j < n) ? g_deg[base + j] : 0;
    int tsum = v[0] + v[1] + v[2] + v[3];
    sm[tid] = tsum;
    __syncthreads();
#pragma unroll
    for (int off = 1; off < 256; off <<= 1) {
        int t2 = (tid >= off) ? sm[tid - off] : 0;
        __syncthreads();
        sm[tid] += t2;
        __syncthreads();
    }
    if (tid == 255) g_blocksum[blockIdx.x] = sm[255];
    int run = sm[tid] - tsum;  // exclusive
#pragma unroll
    for (int j = 0; j < 4; j++) {
        if (base + j < n) g_rowptr[base + j] = run;
        run += v[j];
    }
}

__global__ void scan_top_kernel(int nb) {
    __shared__ int sm[256];
    int tid = threadIdx.x;
    int v = (tid < nb) ? g_blocksum[tid] : 0;
    sm[tid] = v;
    __syncthreads();
#pragma unroll
    for (int off = 1; off < 256; off <<= 1) {
        int t2 = (tid >= off) ? sm[tid - off] : 0;
        __syncthreads();
        sm[tid] += t2;
        __syncthreads();
    }
    if (tid < nb) g_blockoff[tid] = sm[tid] - v;  // exclusive
}

__global__ void scan_add_kernel(int n, int E) {
    int i = blockIdx.x * blockDim.x + threadIdx.x;
    if (i < n) {
        g_rowptr[i] += g_blockoff[i / SCAN_BLK];
        g_cursor[i] = 0;
    } else if (i == n) {
        g_rowptr[n] = E;
    }
}

// ---- bin edges into CSR slots, fusing norm computation ----
__global__ void permute_kernel(const int* __restrict__ src,
                               const int* __restrict__ dst, int E) {
    int e = blockIdx.x * blockDim.x + threadIdx.x;
    if (e < E) {
        int s = src[e];
        int d = dst[e];
        int pos = atomicAdd(&g_cursor[d], 1);
        int slot = g_rowptr[d] + pos;
        g_csrc[slot] = s;
        g_cnorm[slot] = g_dis[s] * g_dis[d];
    }
}

// ---------------- GEMM: out[N,64] = f(in)[N,K] @ W[K,64] ----------------
__device__ __forceinline__ unsigned long long fma2(unsigned long long a,
                                                   unsigned long long b,
                                                   unsigned long long c) {
    unsigned long long d;
    asm("fma.rn.f32x2 %0, %1, %2, %3;" : "=l"(d) : "l"(a), "l"(b), "l"(c));
    return d;
}

template <int K, bool RELU>
__global__ void gemm64_kernel(const float* __restrict__ in,
                              const float* __restrict__ W,
                              float* __restrict__ out, int n) {
    extern __shared__ float sm[];
    float* Ws  = sm;                // K*64 floats
    float* inS = sm + K * 64;       // 32 rows, stride K+4
    const int tid = threadIdx.x;    // 128 threads
    const int STR = K + 4;

    {
        const float4* W4 = (const float4*)W;
        float4* Ws4 = (float4*)Ws;
        for (int i = tid; i < K * 16; i += 128) Ws4[i] = W4[i];
    }
    int base = blockIdx.x * 32;
    {
        const int K4 = K / 4;
        const float4* in4 = (const float4*)(in + (size_t)base * K);
        for (int i = tid; i < 32 * K4; i += 128) {
            int node = i / K4, k4 = i % K4;
            float4 v;
            if (base + node < n) v = in4[i];
            else v = make_float4(0.f, 0.f, 0.f, 0.f);
            if (RELU) {
                v.x = fmaxf(v.x, 0.f); v.y = fmaxf(v.y, 0.f);
                v.z = fmaxf(v.z, 0.f); v.w = fmaxf(v.w, 0.f);
            }
            ((float4*)(inS + node * STR))[k4] = v;
        }
    }
    __syncthreads();

    const int tx = tid & 3;
    const int ty = tid >> 2;

    unsigned long long acc[8];
#pragma unroll
    for (int p = 0; p < 8; p++) acc[p] = 0ull;

    const ulonglong2* WsU2 = (const ulonglong2*)Ws;
    const float* row = inS + ty * STR;

#pragma unroll 8
    for (int k = 0; k < K; k++) {
        float r = row[k];
        unsigned long long rr;
        asm("mov.b64 %0, {%1, %1};" : "=l"(rr) : "f"(r));
#pragma unroll
        for (int j = 0; j < 4; j++) {
            ulonglong2 w = WsU2[k * 16 + tx * 4 + j];
            acc[2 * j]     = fma2(w.x, rr, acc[2 * j]);
            acc[2 * j + 1] = fma2(w.y, rr, acc[2 * j + 1]);
        }
    }

    int node = base + ty;
    if (node < n) {
        ulonglong2* o = (ulonglong2*)(out + (size_t)node * 64 + tx * 16);
#pragma unroll
        for (int j = 0; j < 4; j++) o[j] = make_ulonglong2(acc[2 * j], acc[2 * j + 1]);
    }
}

// ---------------- CSR gather (warp per node, unroll 4, MLP 4) ----------------
// agg[i] = sum_{e in(i)} t[src_e]*norm_e + t[i]*dis_i^2 + b
// 32 lanes x float2 = one 256B row per load. Norms predicated on row end
// (zero contribution); indices read unpredicated (pad is zero-init -> node 0).
__global__ __launch_bounds__(256) void gather_kernel(const float* __restrict__ b,
                                                     int n) {
    int node = blockIdx.x * 8 + (threadIdx.x >> 5);  // 8 warps/block
    int l = threadIdx.x & 31;
    if (node >= n) return;

    int e  = g_rowptr[node];
    int e1 = g_rowptr[node + 1];

    const float2* t2 = (const float2*)g_t;

    float2 acc = make_float2(0.f, 0.f);

    for (; e < e1; e += 4) {
        int s0 = g_csrc[e];
        int s1 = g_csrc[e + 1];
        int s2 = g_csrc[e + 2];
        int s3 = g_csrc[e + 3];
        float n0 = g_cnorm[e];
        float n1 = (e + 1 < e1) ? g_cnorm[e + 1] : 0.f;
        float n2 = (e + 2 < e1) ? g_cnorm[e + 2] : 0.f;
        float n3 = (e + 3 < e1) ? g_cnorm[e + 3] : 0.f;
        float2 v0 = t2[s0 * 32 + l];
        float2 v1 = t2[s1 * 32 + l];
        float2 v2 = t2[s2 * 32 + l];
        float2 v3 = t2[s3 * 32 + l];
        acc.x = fmaf(v0.x, n0, acc.x); acc.y = fmaf(v0.y, n0, acc.y);
        acc.x = fmaf(v1.x, n1, acc.x); acc.y = fmaf(v1.y, n1, acc.y);
        acc.x = fmaf(v2.x, n2, acc.x); acc.y = fmaf(v2.y, n2, acc.y);
        acc.x = fmaf(v3.x, n3, acc.x); acc.y = fmaf(v3.y, n3, acc.y);
    }

    // self-loop + bias
    float s = g_dis[node]; s = s * s;
    float2 v = t2[node * 32 + l];
    float2 bb = ((const float2*)b)[l];
    acc.x = fmaf(v.x, s, acc.x) + bb.x;
    acc.y = fmaf(v.y, s, acc.y) + bb.y;

    ((float2*)g_agg)[node * 32 + l] = acc;
}

// ---------------- pooling + output linear ----------------
__global__ void pool_out_kernel(const int* __restrict__ batch,
                                const float* __restrict__ Wout,
                                const float* __restrict__ bout,
                                float* __restrict__ out,
                                float* __restrict__ pooled, int n) {
    int g = blockIdx.x;
    int c = threadIdx.x;  // 64 threads

    int a = 0, b = n;
    while (a < b) { int m = (a + b) >> 1; if (batch[m] < g) a = m + 1; else b = m; }
    int start = a;
    b = n;
    while (a < b) { int m = (a + b) >> 1; if (batch[m] <= g) a = m + 1; else b = m; }
    int end = a;

    float sum = 0.f, mx = 0.f;
#pragma unroll 4
    for (int i = start; i < end; i++) {
        float v = fmaxf(g_agg[(size_t)i * 64 + c], 0.f);
        sum += v;
        mx = fmaxf(mx, v);
    }
    int cnt = end - start;
    float mean = (cnt > 0) ? sum / (float)cnt : 0.f;

    pooled[(size_t)g * 128 + c] = mean;
    pooled[(size_t)g * 128 + 64 + c] = mx;

    float partial = mean * Wout[c] + mx * Wout[64 + c];
#pragma unroll
    for (int o = 16; o > 0; o >>= 1)
        partial += __shfl_down_sync(0xffffffffu, partial, o);
    __shared__ float ws[2];
    if ((threadIdx.x & 31) == 0) ws[threadIdx.x >> 5] = partial;
    __syncthreads();
    if (threadIdx.x == 0) out[g] = ws[0] + ws[1] + bout[0];
}

// ---------------- host ----------------
extern "C" void kernel_launch(void* const* d_in, const int* in_sizes, int n_in,
                              void* d_out, int out_size) {
    const float* x     = (const float*)d_in[0];
    const int*   edge  = (const int*)d_in[1];     // int64 inputs arrive as int32
    const int*   batch = (const int*)d_in[2];
    const float* W1 = (const float*)d_in[3];  const float* b1 = (const float*)d_in[4];
    const float* W2 = (const float*)d_in[5];  const float* b2 = (const float*)d_in[6];
    const float* W3 = (const float*)d_in[7];  const float* b3 = (const float*)d_in[8];
    const float* W4 = (const float*)d_in[9];  const float* b4 = (const float*)d_in[10];
    const float* Wout = (const float*)d_in[11]; const float* bout = (const float*)d_in[12];

    int N = in_sizes[0] / 128;
    int E = in_sizes[1] / 2;
    int G = out_size / 129;  // out[G,1] + pooled[G,128]

    const int* src = edge;
    const int* dst = edge + E;

    float* out_p    = (float*)d_out;
    float* pooled_p = out_p + G;

    float *tptr = nullptr, *aptr = nullptr;
    int *degptr = nullptr;
    cudaGetSymbolAddress((void**)&tptr, g_t);
    cudaGetSymbolAddress((void**)&aptr, g_agg);
    cudaGetSymbolAddress((void**)&degptr, g_deg);

    const int smem128 = (128 * 64 + 32 * (128 + 4)) * (int)sizeof(float);
    const int smem64  = (64 * 64 + 32 * (64 + 4)) * (int)sizeof(float);
    cudaFuncSetAttribute(gemm64_kernel<128, false>,
                         cudaFuncAttributeMaxDynamicSharedMemorySize, smem128);
    cudaFuncSetAttribute(gemm64_kernel<64, true>,
                         cudaFuncAttributeMaxDynamicSharedMemorySize, smem64);

    // ---- degree + CSR build ----
    cudaMemsetAsync(degptr, 0, N * sizeof(int));
    count_deg_kernel<<<(E + 255) / 256, 256>>>(dst, E);
    compute_dis_kernel<<<(N + 255) / 256, 256>>>(N);

    int nsb = (N + SCAN_BLK - 1) / SCAN_BLK;       // <= 98 for N=100K
    scan_part_kernel<<<nsb, 256>>>(N);
    scan_top_kernel<<<1, 256>>>(nsb);
    scan_add_kernel<<<(N + 256) / 256, 256>>>(N, E);
    permute_kernel<<<(E + 255) / 256, 256>>>(src, dst, E);

    int gblocks  = (N + 31) / 32;
    int agblocks = (N + 7) / 8;

    // layer 1
    gemm64_kernel<128, false><<<gblocks, 128, smem128>>>(x, W1, tptr, N);
    gather_kernel<<<agblocks, 256>>>(b1, N);
    // layers 2..4
    gemm64_kernel<64, true><<<gblocks, 128, smem64>>>(aptr, W2, tptr, N);
    gather_kernel<<<agblocks, 256>>>(b2, N);

    gemm64_kernel<64, true><<<gblocks, 128, smem64>>>(aptr, W3, tptr, N);
    gather_kernel<<<agblocks, 256>>>(b3, N);

    gemm64_kernel<64, true><<<gblocks, 128, smem64>>>(aptr, W4, tptr, N);
    gather_kernel<<<agblocks, 256>>>(b4, N);

    // pooling (+ fused output linear), relu of layer 4 fused in
    pool_out_kernel<<<G, 64>>>(batch, Wout, bout, out_p, pooled_p, N);
}

// round 5
// speedup vs baseline: 1.0391x; 1.0391x over previous
#include <cuda_runtime.h>
#include <cuda_fp16.h>

#define MAXN 100000
#define MAXE 1600000
#define HID 64
#define SCAN_BLK 1024
#define MAX_SCAN_BLOCKS 256

// ---- scratch (device globals; no allocation allowed) ----
__device__ __align__(256) __half g_t16[MAXN * HID];   // h @ W  (fp16 storage)
__device__ __align__(256) float g_agg[MAXN * HID];    // aggregated messages (fp32)
__device__ __align__(256) float g_dis[MAXN];          // deg^{-1/2}
__device__ __align__(256) int   g_deg[MAXN];
__device__ __align__(256) int   g_rowptr[MAXN + 1];   // CSR row pointers (by dst)
__device__ __align__(256) int   g_cursor[MAXN];
__device__ __align__(256) int   g_blocksum[MAX_SCAN_BLOCKS];
__device__ __align__(256) int   g_blockoff[MAX_SCAN_BLOCKS];
__device__ __align__(256) int2  g_edge[MAXE + 4];     // CSR slot: (src, norm-bits); +4 pad stays 0

// ---------------- prep ----------------
__global__ void count_deg_kernel(const int* __restrict__ dst, int E) {
    int e = blockIdx.x * blockDim.x + threadIdx.x;
    if (e < E) atomicAdd(&g_deg[dst[e]], 1);
}

// ---- exclusive scan of g_deg -> g_rowptr; also computes dis = rsqrt(deg+1) ----
__global__ void scan_part_kernel(int n) {
    __shared__ int sm[256];
    int tid = threadIdx.x;
    int base = blockIdx.x * SCAN_BLK + tid * 4;
    int v[4];
#pragma unroll
    for (int j = 0; j < 4; j++) {
        v[j] = (base + j < n) ? g_deg[base + j] : 0;
        if (base + j < n) g_dis[base + j] = rsqrtf((float)(v[j] + 1));
    }
    int tsum = v[0] + v[1] + v[2] + v[3];
    sm[tid] = tsum;
    __syncthreads();
#pragma unroll
    for (int off = 1; off < 256; off <<= 1) {
        int t2 = (tid >= off) ? sm[tid - off] : 0;
        __syncthreads();
        sm[tid] += t2;
        __syncthreads();
    }
    if (tid == 255) g_blocksum[blockIdx.x] = sm[255];
    int run = sm[tid] - tsum;  // exclusive
#pragma unroll
    for (int j = 0; j < 4; j++) {
        if (base + j < n) g_rowptr[base + j] = run;
        run += v[j];
    }
}

__global__ void scan_top_kernel(int nb) {
    __shared__ int sm[256];
    int tid = threadIdx.x;
    int v = (tid < nb) ? g_blocksum[tid] : 0;
    sm[tid] = v;
    __syncthreads();
#pragma unroll
    for (int off = 1; off < 256; off <<= 1) {
        int t2 = (tid >= off) ? sm[tid - off] : 0;
        __syncthreads();
        sm[tid] += t2;
        __syncthreads();
    }
    if (tid < nb) g_blockoff[tid] = sm[tid] - v;  // exclusive
}

__global__ void scan_add_kernel(int n, int E) {
    int i = blockIdx.x * blockDim.x + threadIdx.x;
    if (i < n) {
        g_rowptr[i] += g_blockoff[i / SCAN_BLK];
        g_cursor[i] = 0;
    } else if (i == n) {
        g_rowptr[n] = E;
    }
}

// ---- bin edges into CSR slots, fusing norm computation ----
__global__ void permute_kernel(const int* __restrict__ src,
                               const int* __restrict__ dst, int E) {
    int e = blockIdx.x * blockDim.x + threadIdx.x;
    if (e < E) {
        int s = src[e];
        int d = dst[e];
        int pos = atomicAdd(&g_cursor[d], 1);
        int slot = g_rowptr[d] + pos;
        g_edge[slot] = make_int2(s, __float_as_int(g_dis[s] * g_dis[d]));
    }
}

// ---------------- GEMM: t16[N,64] = f(in)[N,K] @ W[K,64]  (fp16 out) ----------------
__device__ __forceinline__ unsigned long long fma2(unsigned long long a,
                                                   unsigned long long b,
                                                   unsigned long long c) {
    unsigned long long d;
    asm("fma.rn.f32x2 %0, %1, %2, %3;" : "=l"(d) : "l"(a), "l"(b), "l"(c));
    return d;
}

template <int K, bool RELU>
__global__ void gemm64_kernel(const float* __restrict__ in,
                              const float* __restrict__ W,
                              __half* __restrict__ out, int n) {
    extern __shared__ float sm[];
    float* Ws  = sm;                // K*64 floats
    float* inS = sm + K * 64;       // 32 rows, stride K+4
    const int tid = threadIdx.x;    // 128 threads
    const int STR = K + 4;

    {
        const float4* W4 = (const float4*)W;
        float4* Ws4 = (float4*)Ws;
        for (int i = tid; i < K * 16; i += 128) Ws4[i] = W4[i];
    }
    int base = blockIdx.x * 32;
    {
        const int K4 = K / 4;
        const float4* in4 = (const float4*)(in + (size_t)base * K);
        for (int i = tid; i < 32 * K4; i += 128) {
            int node = i / K4, k4 = i % K4;
            float4 v;
            if (base + node < n) v = in4[i];
            else v = make_float4(0.f, 0.f, 0.f, 0.f);
            if (RELU) {
                v.x = fmaxf(v.x, 0.f); v.y = fmaxf(v.y, 0.f);
                v.z = fmaxf(v.z, 0.f); v.w = fmaxf(v.w, 0.f);
            }
            ((float4*)(inS + node * STR))[k4] = v;
        }
    }
    __syncthreads();

    const int tx = tid & 3;
    const int ty = tid >> 2;

    unsigned long long acc[8];
#pragma unroll
    for (int p = 0; p < 8; p++) acc[p] = 0ull;

    const ulonglong2* WsU2 = (const ulonglong2*)Ws;
    const float* row = inS + ty * STR;

#pragma unroll 8
    for (int k = 0; k < K; k++) {
        float r = row[k];
        unsigned long long rr;
        asm("mov.b64 %0, {%1, %1};" : "=l"(rr) : "f"(r));
#pragma unroll
        for (int j = 0; j < 4; j++) {
            ulonglong2 w = WsU2[k * 16 + tx * 4 + j];
            acc[2 * j]     = fma2(w.x, rr, acc[2 * j]);
            acc[2 * j + 1] = fma2(w.y, rr, acc[2 * j + 1]);
        }
    }

    int node = base + ty;
    if (node < n) {
        unsigned int res[8];
#pragma unroll
        for (int j = 0; j < 8; j++) {
            float lo = __uint_as_float((unsigned int)(acc[j] & 0xffffffffull));
            float hi = __uint_as_float((unsigned int)(acc[j] >> 32));
            __half2 h = __floats2half2_rn(lo, hi);
            res[j] = *(unsigned int*)&h;
        }
        uint4* o = (uint4*)(out + (size_t)node * 64 + tx * 16);
        o[0] = make_uint4(res[0], res[1], res[2], res[3]);
        o[1] = make_uint4(res[4], res[5], res[6], res[7]);
    }
}

// ---------------- CSR gather (warp per node, fp16 rows, packed idx) --------
// agg[i] = sum_{e in(i)} t[src_e]*norm_e + t[i]*dis_i^2 + b
// 32 lanes x half2 = one 128B row per edge (1 wavefront). One LDG.64 per edge
// for (src, norm). Pad entries are zero-init -> norm 0, contribute nothing.
__global__ __launch_bounds__(256) void gather_kernel(const float* __restrict__ b,
                                                     int n) {
    int node = blockIdx.x * 8 + (threadIdx.x >> 5);  // 8 warps/block
    int l = threadIdx.x & 31;
    if (node >= n) return;

    int e  = g_rowptr[node];
    int e1 = g_rowptr[node + 1];

    const __half2* t2 = (const __half2*)g_t16;

    float2 acc = make_float2(0.f, 0.f);

    for (; e < e1; e += 4) {
        int2 p0 = g_edge[e];
        int2 p1 = g_edge[e + 1];
        int2 p2 = g_edge[e + 2];
        int2 p3 = g_edge[e + 3];
        float n0 = __int_as_float(p0.y);
        float n1 = (e + 1 < e1) ? __int_as_float(p1.y) : 0.f;
        float n2 = (e + 2 < e1) ? __int_as_float(p2.y) : 0.f;
        float n3 = (e + 3 < e1) ? __int_as_float(p3.y) : 0.f;
        float2 f0 = __half22float2(t2[p0.x * 32 + l]);
        float2 f1 = __half22float2(t2[p1.x * 32 + l]);
        float2 f2 = __half22float2(t2[p2.x * 32 + l]);
        float2 f3 = __half22float2(t2[p3.x * 32 + l]);
        acc.x = fmaf(f0.x, n0, acc.x); acc.y = fmaf(f0.y, n0, acc.y);
        acc.x = fmaf(f1.x, n1, acc.x); acc.y = fmaf(f1.y, n1, acc.y);
        acc.x = fmaf(f2.x, n2, acc.x); acc.y = fmaf(f2.y, n2, acc.y);
        acc.x = fmaf(f3.x, n3, acc.x); acc.y = fmaf(f3.y, n3, acc.y);
    }

    // self-loop + bias
    float s = g_dis[node]; s = s * s;
    float2 v = __half22float2(t2[node * 32 + l]);
    float2 bb = ((const float2*)b)[l];
    acc.x = fmaf(v.x, s, acc.x) + bb.x;
    acc.y = fmaf(v.y, s, acc.y) + bb.y;

    ((float2*)g_agg)[node * 32 + l] = acc;
}

// ---------------- pooling + output linear ----------------
__global__ void pool_out_kernel(const int* __restrict__ batch,
                                const float* __restrict__ Wout,
                                const float* __restrict__ bout,
                                float* __restrict__ out,
                                float* __restrict__ pooled, int n) {
    int g = blockIdx.x;
    int c = threadIdx.x;  // 64 threads

    int a = 0, b = n;
    while (a < b) { int m = (a + b) >> 1; if (batch[m] < g) a = m + 1; else b = m; }
    int start = a;
    b = n;
    while (a < b) { int m = (a + b) >> 1; if (batch[m] <= g) a = m + 1; else b = m; }
    int end = a;

    float sum = 0.f, mx = 0.f;
#pragma unroll 4
    for (int i = start; i < end; i++) {
        float v = fmaxf(g_agg[(size_t)i * 64 + c], 0.f);
        sum += v;
        mx = fmaxf(mx, v);
    }
    int cnt = end - start;
    float mean = (cnt > 0) ? sum / (float)cnt : 0.f;

    pooled[(size_t)g * 128 + c] = mean;
    pooled[(size_t)g * 128 + 64 + c] = mx;

    float partial = mean * Wout[c] + mx * Wout[64 + c];
#pragma unroll
    for (int o = 16; o > 0; o >>= 1)
        partial += __shfl_down_sync(0xffffffffu, partial, o);
    __shared__ float ws[2];
    if ((threadIdx.x & 31) == 0) ws[threadIdx.x >> 5] = partial;
    __syncthreads();
    if (threadIdx.x == 0) out[g] = ws[0] + ws[1] + bout[0];
}

// ---------------- host ----------------
extern "C" void kernel_launch(void* const* d_in, const int* in_sizes, int n_in,
                              void* d_out, int out_size) {
    const float* x     = (const float*)d_in[0];
    const int*   edge  = (const int*)d_in[1];     // int64 inputs arrive as int32
    const int*   batch = (const int*)d_in[2];
    const float* W1 = (const float*)d_in[3];  const float* b1 = (const float*)d_in[4];
    const float* W2 = (const float*)d_in[5];  const float* b2 = (const float*)d_in[6];
    const float* W3 = (const float*)d_in[7];  const float* b3 = (const float*)d_in[8];
    const float* W4 = (const float*)d_in[9];  const float* b4 = (const float*)d_in[10];
    const float* Wout = (const float*)d_in[11]; const float* bout = (const float*)d_in[12];

    int N = in_sizes[0] / 128;
    int E = in_sizes[1] / 2;
    int G = out_size / 129;  // out[G,1] + pooled[G,128]

    const int* src = edge;
    const int* dst = edge + E;

    float* out_p    = (float*)d_out;
    float* pooled_p = out_p + G;

    __half* tptr = nullptr;
    float*  aptr = nullptr;
    int*    degptr = nullptr;
    cudaGetSymbolAddress((void**)&tptr, g_t16);
    cudaGetSymbolAddress((void**)&aptr, g_agg);
    cudaGetSymbolAddress((void**)&degptr, g_deg);

    const int smem128 = (128 * 64 + 32 * (128 + 4)) * (int)sizeof(float);
    const int smem64  = (64 * 64 + 32 * (64 + 4)) * (int)sizeof(float);
    cudaFuncSetAttribute(gemm64_kernel<128, false>,
                         cudaFuncAttributeMaxDynamicSharedMemorySize, smem128);
    cudaFuncSetAttribute(gemm64_kernel<64, true>,
                         cudaFuncAttributeMaxDynamicSharedMemorySize, smem64);

    // ---- degree + CSR build ----
    cudaMemsetAsync(degptr, 0, N * sizeof(int));
    count_deg_kernel<<<(E + 255) / 256, 256>>>(dst, E);

    int nsb = (N + SCAN_BLK - 1) / SCAN_BLK;       // <= 98 for N=100K
    scan_part_kernel<<<nsb, 256>>>(N);
    scan_top_kernel<<<1, 256>>>(nsb);
    scan_add_kernel<<<(N + 256) / 256, 256>>>(N, E);
    permute_kernel<<<(E + 255) / 256, 256>>>(src, dst, E);

    int gblocks  = (N + 31) / 32;
    int agblocks = (N + 7) / 8;

    // layer 1
    gemm64_kernel<128, false><<<gblocks, 128, smem128>>>(x, W1, tptr, N);
    gather_kernel<<<agblocks, 256>>>(b1, N);
    // layers 2..4
    gemm64_kernel<64, true><<<gblocks, 128, smem64>>>(aptr, W2, tptr, N);
    gather_kernel<<<agblocks, 256>>>(b2, N);

    gemm64_kernel<64, true><<<gblocks, 128, smem64>>>(aptr, W3, tptr, N);
    gather_kernel<<<agblocks, 256>>>(b3, N);

    gemm64_kernel<64, true><<<gblocks, 128, smem64>>>(aptr, W4, tptr, N);
    gather_kernel<<<agblocks, 256>>>(b4, N);

    // pooling (+ fused output linear), relu of layer 4 fused in
    pool_out_kernel<<<G, 64>>>(batch, Wout, bout, out_p, pooled_p, N);
}